// round 11
// baseline (speedup 1.0000x reference)
#include <cuda_runtime.h>
#include <math.h>

#define NN 50000
#define NE 400000
#define NG 64
#define DIN 200
#define DH 32
#define NBLK 196    // ceil(NN/256)
#define EBLK2 782   // ceil(NE/512)  (hist: 256 thr x 2 edges)
#define GBLK 391    // ceil(NN/128)  (GEMM blocks: 128 thr, 128 nodes, 64 cols)
#define SCB 1563    // ceil(NE/256)  (scatter blocks: 128 thr x 2 edges)
#define FBLK 6250   // ceil(NN/8)    (flayer/pool blocks: 8 warps, warp per node)

typedef unsigned long long ull;

// ---------------- scratch (device globals — no allocation allowed) ----------
// NOTE: never pass these as kernel args from host code (host shadow symbol +
// ATS silently reads zeros). Select ping-pong buffers with an int in device code.
// Zero-init invariant: g_cnt/g_total/g_sums/g_done are zero at every
// kernel_launch entry — BSS zero covers call 1; the pool kernel's tail resets
// them for subsequent calls.
__device__ __align__(16) float g_tr_a[NN * DH];
__device__ __align__(16) float g_tr_b[NN * DH];
__device__ __align__(16) float g_root_a[NN * DH];
__device__ __align__(16) float g_root_b[NN * DH];
__device__ float g_sums[NG * DH];

__device__ int g_flag_ei;    // nonzero -> edge_index is int32 (set by k_hist blk 0)
__device__ int g_flag_b;     // nonzero -> batch is int32 (set by k_scan_bounds blk 0)

__device__ int g_cnt[NN];
__device__ int g_off[NN];
__device__ int g_cur[NN];
__device__ int g_total;
__device__ int g_done;
__device__ int g_esrc[NE];
__device__ int g_gstart[NG + 1];

__device__ __forceinline__ float elu1(float v) { return v > 0.f ? v : expm1f(v); }

#define FMA_X2(acc, a, b) \
    asm("fma.rn.f32x2 %0, %1, %2, %0;" : "+l"(acc) : "l"(a), "l"(b))
#define DUP_X2(out, x) \
    asm("mov.b64 %0, {%1, %1};" : "=l"(out) : "r"(__float_as_uint(x)))
#define UNPK_X2(lo, hi, in) \
    asm("mov.b64 {%0, %1}, %2;" : "=f"(lo), "=f"(hi) : "l"(in))
#define PACK_X2(out, lo, hi) \
    asm("mov.b64 %0, {%1, %2};" : "=l"(out) : "f"(lo), "f"(hi))

// ---------------------------------------------------------------------------
// dtype decode helpers (clamped)
// ---------------------------------------------------------------------------
__device__ __forceinline__ int edge_at(const void* ei_raw, int idx, int is32)
{
    int v = is32 ? ((const int*)ei_raw)[idx] : (int)((const long long*)ei_raw)[idx];
    v &= 0x7fffffff;
    return (v < NN) ? v : 0;
}

__device__ __forceinline__ int batch_at(const void* b_raw, int i, int is32)
{
    int g = is32 ? ((const int*)b_raw)[i] : (int)((const long long*)b_raw)[i];
    g &= 0x7fffffff;
    return (g < NG) ? g : (NG - 1);
}

// ---------------------------------------------------------------------------
// Kernel 1: dst histogram. Per-block dtype detection (sample odd 32-bit words:
// int64 values < 2^31 have zero high words; int32 payloads essentially never
// do). Block 0 publishes g_flag_ei for later launches. g_cnt is pre-zeroed by
// the zero-invariant.
// ---------------------------------------------------------------------------
__global__ void k_hist(const unsigned* __restrict__ ei_w)
{
    __shared__ int s_flag;
    const int tid = threadIdx.x;
    if (tid == 0) s_flag = 0;
    __syncthreads();
    { const int k = tid * 1562; if (ei_w[2 * k + 1] != 0) atomicOr(&s_flag, 1); }
    __syncthreads();
    const int is32 = s_flag;
    if (blockIdx.x == 0 && tid == 0) g_flag_ei = is32;

    const int base = blockIdx.x * 256 + tid;
#pragma unroll
    for (int q = 0; q < 2; q++) {
        const int e = base + q * (EBLK2 * 256);
        if (e < NE) atomicAdd(&g_cnt[edge_at(ei_w, NE + e, is32)], 1);
    }
}

// ---------------------------------------------------------------------------
// Kernel 2: single-pass scan (block scan + atomic base; bases need not be
// monotone since consumers use beg + cnt) fused with graph-boundary build.
// Per-block batch dtype detection; block 0 publishes g_flag_b.
// ---------------------------------------------------------------------------
__global__ void k_scan_bounds(const void* __restrict__ b_raw)
{
    __shared__ int s[256];
    __shared__ int base_sh;
    __shared__ int s_flag;
    const int tid = threadIdx.x;
    if (tid == 0) s_flag = 0;
    __syncthreads();
    {   // sample sorted tail (values ~ NG-1): odd words nonzero iff int32
        const unsigned* bw = (const unsigned*)b_raw;
        const int k = 24744 + tid;
        if (bw[2 * k + 1] != 0) atomicOr(&s_flag, 1);
    }

    const int i = blockIdx.x * 256 + tid;
    const int v = (i < NN) ? g_cnt[i] : 0;
    s[tid] = v;
    __syncthreads();
    const int is32 = s_flag;
    if (blockIdx.x == 0 && tid == 0) g_flag_b = is32;
#pragma unroll
    for (int d = 1; d < 256; d <<= 1) {
        const int t = (tid >= d) ? s[tid - d] : 0;
        __syncthreads();
        s[tid] += t;
        __syncthreads();
    }
    if (tid == 255) base_sh = atomicAdd(&g_total, s[255]);
    __syncthreads();
    if (i < NN) {
        const int o = base_sh + s[tid] - v;
        g_off[i] = o;
        g_cur[i] = o;
    }

    if (i < NN) {
        const int g  = batch_at(b_raw, i, is32);
        const int gp = (i == 0) ? -1 : batch_at(b_raw, i - 1, is32);
        for (int q = gp + 1; q <= g; q++) g_gstart[q] = i;
        if (i == NN - 1)
            for (int q = g + 1; q <= NG; q++) g_gstart[q] = NN;
    }
}

// ---------------------------------------------------------------------------
// Kernel 3 (fused): blocks [0,GBLK) = GEMM1; blocks [GBLK,GBLK+SCB) = CSR
// scatter (decodes raw edges; g_flag_ei set by k_hist launch).
// GEMM1: [50000,200] @ [W1r|W1l][200,64]. Node-pair f32x2 packing:
//   acc pair = (node 2i, node 2i+1), W pre-DUPLICATED in smem during staging
//   -> inner loop has ZERO mov.b64 dups, 38 instr/kk vs 46.
// 128 threads / 128 nodes / 64 cols, double-buffered, 1 barrier per K-tile.
// ---------------------------------------------------------------------------
__global__ __launch_bounds__(128) void k_gemm1_scatter(const float* __restrict__ x,
                                                       const float* __restrict__ Wr,
                                                       const float* __restrict__ Wl,
                                                       const float* __restrict__ b,
                                                       const void* __restrict__ ei_raw)
{
    if (blockIdx.x >= GBLK) {
        const int base = (blockIdx.x - GBLK) * 256 + threadIdx.x;
        const int is32 = g_flag_ei;
#pragma unroll
        for (int q = 0; q < 2; q++) {
            const int e = base + q * 128;
            if (e < NE) {
                const int d = edge_at(ei_raw, NE + e, is32);
                const int sres = edge_at(ei_raw, e, is32);
                const int pos = atomicAdd(&g_cur[d], 1);
                g_esrc[pos] = sres;
            }
        }
        return;
    }

    __shared__ __align__(16) float Xs[2][8 * 128];   // [buf][k][node]
    __shared__ __align__(16) ull   Wd[2][8 * 64];    // [buf][k*64+c] = (w,w)
    __shared__ float bs[32];

    const int tid = threadIdx.x;
    const int n0  = blockIdx.x * 128;
    if (tid < 32) bs[tid] = b[tid];

    const int cg = tid & 7;        // col group (8 cols)
    const int ng = tid >> 3;       // node group (8 nodes = 4 pairs), 0..15

    ull acc2[4][8];                // [node pair][col]
#pragma unroll
    for (int i = 0; i < 4; i++)
#pragma unroll
        for (int j = 0; j < 8; j++) acc2[i][j] = 0ULL;

    const int  nld = n0 + tid;
    const bool vld = nld < NN;
    const float4* xrow = reinterpret_cast<const float4*>(x + (long)nld * DIN);

    float4 xa, xb;
    float  wv[4];

#define LOAD_TILE(t)                                                          \
    do {                                                                      \
        xa = make_float4(0.f, 0.f, 0.f, 0.f); xb = xa;                        \
        if (vld) { xa = xrow[(t) * 2]; xb = xrow[(t) * 2 + 1]; }              \
        _Pragma("unroll")                                                     \
        for (int j = 0; j < 4; j++) {                                         \
            const int idx = j * 128 + tid;       /* 0..511 = kk*64+c */       \
            const int kk = idx >> 6, c = idx & 63;                            \
            wv[j] = (c < 32) ? Wr[((t) * 8 + kk) * 32 + c]                    \
                             : Wl[((t) * 8 + kk) * 32 + c - 32];              \
        }                                                                     \
    } while (0)

#define STORE_TILE(bf)                                                        \
    do {                                                                      \
        Xs[bf][0 * 128 + tid] = xa.x; Xs[bf][1 * 128 + tid] = xa.y;           \
        Xs[bf][2 * 128 + tid] = xa.z; Xs[bf][3 * 128 + tid] = xa.w;           \
        Xs[bf][4 * 128 + tid] = xb.x; Xs[bf][5 * 128 + tid] = xb.y;           \
        Xs[bf][6 * 128 + tid] = xb.z; Xs[bf][7 * 128 + tid] = xb.w;           \
        _Pragma("unroll")                                                     \
        for (int j = 0; j < 4; j++) {                                         \
            ull wd; DUP_X2(wd, wv[j]);                                        \
            Wd[bf][j * 128 + tid] = wd;                                       \
        }                                                                     \
    } while (0)

    LOAD_TILE(0);
    STORE_TILE(0);
    __syncthreads();

    int buf = 0;
    for (int t = 0; t < 25; t++) {
        if (t < 24) LOAD_TILE(t + 1);                // LDG in flight during compute

#pragma unroll
        for (int kk = 0; kk < 8; kk++) {
            const ull* xp = reinterpret_cast<const ull*>(Xs[buf] + kk * 128 + ng * 8);
            const ull xp0 = xp[0], xp1 = xp[1], xp2 = xp[2], xp3 = xp[3];
            const ull* wp = Wd[buf] + kk * 64 + cg * 8;
#pragma unroll
            for (int j = 0; j < 8; j++) {
                const ull wdj = wp[j];
                FMA_X2(acc2[0][j], xp0, wdj);
                FMA_X2(acc2[1][j], xp1, wdj);
                FMA_X2(acc2[2][j], xp2, wdj);
                FMA_X2(acc2[3][j], xp3, wdj);
            }
        }

        if (t < 24) STORE_TILE(buf ^ 1);             // other buffer: race-free
        __syncthreads();
        buf ^= 1;
    }
#undef LOAD_TILE
#undef STORE_TILE

    const int c0 = cg * 8;
#pragma unroll
    for (int i = 0; i < 4; i++) {
        const int ne = n0 + ng * 8 + 2 * i;          // even node of pair
        float lo[8], hi[8];
#pragma unroll
        for (int j = 0; j < 8; j++) UNPK_X2(lo[j], hi[j], acc2[i][j]);

#pragma unroll
        for (int p = 0; p < 2; p++) {
            const int node = ne + p;
            if (node >= NN) continue;
            const float* c = p ? hi : lo;
            float4 v0 = make_float4(c[0], c[1], c[2], c[3]);
            float4 v1 = make_float4(c[4], c[5], c[6], c[7]);
            if (cg < 4) {
                *reinterpret_cast<float4*>(g_tr_a + node * DH + c0)     = v0;
                *reinterpret_cast<float4*>(g_tr_a + node * DH + c0 + 4) = v1;
            } else {
                const int cc = c0 - 32;
                v0.x += bs[cc + 0]; v0.y += bs[cc + 1]; v0.z += bs[cc + 2]; v0.w += bs[cc + 3];
                v1.x += bs[cc + 4]; v1.y += bs[cc + 5]; v1.z += bs[cc + 6]; v1.w += bs[cc + 7];
                *reinterpret_cast<float4*>(g_root_a + node * DH + cc)     = v0;
                *reinterpret_cast<float4*>(g_root_a + node * DH + cc + 4) = v1;
            }
        }
    }
}

// ---------------------------------------------------------------------------
// Fused layer kernel (layers 1->2, 2->3): warp per node (round-8 proven).
// Buffers picked by sel in device code (sel=0: a->b, sel=1: b->a).
// ---------------------------------------------------------------------------
__global__ __launch_bounds__(256) void k_flayer(int sel,
                                                const float* __restrict__ Wr,
                                                const float* __restrict__ Wl,
                                                const float* __restrict__ b)
{
    __shared__ __align__(16) ull Wp[32 * 32];  // [k][lane]=(Wr,Wl)
    __shared__ float bs[32];
    __shared__ float hs[8][32];

    const int tid = threadIdx.x;
    for (int i = tid; i < 1024; i += 256) {
        const int k = i >> 5, c = i & 31;
        ull p;
        PACK_X2(p, Wr[k * 32 + c], Wl[k * 32 + c]);
        Wp[i] = p;
    }
    if (tid < 32) bs[tid] = b[tid];
    __syncthreads();

    const float* tr_in   = sel ? g_tr_b   : g_tr_a;
    const float* root_in = sel ? g_root_b : g_root_a;
    float* tr_out   = sel ? g_tr_a   : g_tr_b;
    float* root_out = sel ? g_root_a : g_root_b;

    const int w    = tid >> 5;
    const int lane = tid & 31;
    const int node = (blockIdx.x << 3) + w;
    if (node >= NN) return;

    const int beg = g_off[node];
    const int end = beg + g_cnt[node];
    float acc = 0.f;
    int k = beg;
    for (; k + 3 < end; k += 4) {
        const int s0 = g_esrc[k + 0], s1 = g_esrc[k + 1];
        const int s2 = g_esrc[k + 2], s3 = g_esrc[k + 3];
        acc += tr_in[s0 * DH + lane] + tr_in[s1 * DH + lane]
             + tr_in[s2 * DH + lane] + tr_in[s3 * DH + lane];
    }
    for (; k < end; k++) acc += tr_in[g_esrc[k] * DH + lane];

    const float h = elu1(acc + root_in[node * DH + lane]);
    hs[w][lane] = h;
    __syncwarp();

    ull a2 = 0ULL;
#pragma unroll
    for (int kk = 0; kk < 32; kk++) {
        ull hd;
        DUP_X2(hd, hs[w][kk]);                    // LDS broadcast
        FMA_X2(a2, hd, Wp[kk * 32 + lane]);
    }
    float m, r;
    UNPK_X2(m, r, a2);
    tr_out[node * DH + lane]   = m;
    root_out[node * DH + lane] = r + bs[lane];
}

// ---------------------------------------------------------------------------
// Fused layer 3 + pool + head: reads a-buffers; h = elu(aggr + root);
// atomicAdd into per-graph sums. Last block (threadfence + counter) computes
// the head (mean -> linear -> log_softmax) and resets scratch to zero for the
// next call (zero-invariant). Also zeroes g_cnt per node after final use.
// ---------------------------------------------------------------------------
__global__ __launch_bounds__(256) void k_flayer3_pool(const void* __restrict__ b_raw,
                                                      const float* __restrict__ Wlin,
                                                      const float* __restrict__ blin,
                                                      float* __restrict__ out)
{
    __shared__ int s_last;
    const int tid  = threadIdx.x;
    const int w    = tid >> 5;
    const int lane = tid & 31;
    const int node = (blockIdx.x << 3) + w;
    const int is32b = g_flag_b;

    if (node < NN) {
        const int beg = g_off[node];
        const int cnt = g_cnt[node];
        const int end = beg + cnt;
        float acc = 0.f;
        int k = beg;
        for (; k + 3 < end; k += 4) {
            const int s0 = g_esrc[k + 0], s1 = g_esrc[k + 1];
            const int s2 = g_esrc[k + 2], s3 = g_esrc[k + 3];
            acc += g_tr_a[s0 * DH + lane] + g_tr_a[s1 * DH + lane]
                 + g_tr_a[s2 * DH + lane] + g_tr_a[s3 * DH + lane];
        }
        for (; k < end; k++) acc += g_tr_a[g_esrc[k] * DH + lane];

        const float h = elu1(acc + g_root_a[node * DH + lane]);
        const int g = batch_at(b_raw, node, is32b);
        atomicAdd(&g_sums[g * DH + lane], h);
        if (lane == 0) g_cnt[node] = 0;            // reset for next call
    }

    // last-block head
    __syncthreads();
    if (tid == 0) {
        __threadfence();
        const int v = atomicAdd(&g_done, 1);
        s_last = (v == FBLK - 1);
    }
    __syncthreads();
    if (!s_last) return;

    float l0 = 0.f, l1 = 0.f;
    if (tid < NG) {
        const int cnt = g_gstart[tid + 1] - g_gstart[tid];
        const float inv = 1.f / fmaxf((float)cnt, 1.f);
        l0 = blin[0]; l1 = blin[1];
#pragma unroll
        for (int c = 0; c < DH; c++) {
            const float p = g_sums[tid * DH + c] * inv;
            l0 += p * Wlin[c * 2 + 0];
            l1 += p * Wlin[c * 2 + 1];
        }
    }
    __syncthreads();                                // reads done before resets
    if (tid < NG) {
        const float m   = fmaxf(l0, l1);
        const float lse = m + logf(expf(l0 - m) + expf(l1 - m));
        out[tid * 2 + 0] = l0 - lse;
        out[tid * 2 + 1] = l1 - lse;
    }
    // reset scratch (zero-invariant for next call)
    for (int i = tid; i < NG * DH; i += 256) g_sums[i] = 0.f;
    if (tid == 0) { g_total = 0; g_done = 0; }
}

// ---------------------------------------------------------------------------
extern "C" void kernel_launch(void* const* d_in, const int* in_sizes, int n_in,
                              void* d_out, int out_size)
{
    const void *p_x = 0, *p_ei = 0, *p_batch = 0;
    const void *p_W1[2] = {0, 0};
    const void *p_W23[4] = {0, 0, 0, 0};
    const void *p_b[3] = {0, 0, 0};
    const void *p_Wlin = 0, *p_blin = 0;
    int n64 = 0, n1024 = 0, n32 = 0;
    for (int i = 0; i < n_in; i++) {
        const int s = in_sizes[i];
        if      (s == NN * DIN) p_x = d_in[i];
        else if (s == 2 * NE)   p_ei = d_in[i];
        else if (s == NN)       p_batch = d_in[i];
        else if (s == DIN * DH) { if (n64 < 2) p_W1[n64++] = d_in[i]; }
        else if (s == DH * DH)  { if (n1024 < 4) p_W23[n1024++] = d_in[i]; }
        else if (s == DH)       { if (n32 < 3) p_b[n32++] = d_in[i]; }
        else if (s == DH * 2)   p_Wlin = d_in[i];
        else if (s == 2)        p_blin = d_in[i];
    }
    const float* x    = (const float*)p_x;
    const float* W1r  = (const float*)p_W1[0];
    const float* W1l  = (const float*)p_W1[1];
    const float* b1   = (const float*)p_b[0];
    const float* W2r  = (const float*)p_W23[0];
    const float* W2l  = (const float*)p_W23[1];
    const float* b2   = (const float*)p_b[1];
    const float* W3r  = (const float*)p_W23[2];
    const float* W3l  = (const float*)p_W23[3];
    const float* b3   = (const float*)p_b[2];
    const float* Wlin = (const float*)p_Wlin;
    const float* blin = (const float*)p_blin;
    float* out = (float*)d_out;

    k_hist<<<EBLK2, 256>>>((const unsigned*)p_ei);
    k_scan_bounds<<<NBLK, 256>>>(p_batch);
    k_gemm1_scatter<<<GBLK + SCB, 128>>>(x, W1r, W1l, b1, p_ei);
    k_flayer<<<FBLK, 256>>>(0, W2r, W2l, b2);     // a -> b (L1 act + L2 linear)
    k_flayer<<<FBLK, 256>>>(1, W3r, W3l, b3);     // b -> a (L2 act + L3 linear)
    k_flayer3_pool<<<FBLK, 256>>>(p_batch, Wlin, blin, out);  // L3 act + pool + head
}